// round 15
// baseline (speedup 1.0000x reference)
#include <cuda_runtime.h>
#include <cuda_fp16.h>
#include <cstdint>

// ============================ problem constants ============================
#define SS 2048
#define DD 4096
#define VV 32000
#define MROWS 4094          // B*(S-1)
#define MPAD  4096          // padded GEMM M

// scratch (device globals — allocation-free rule), fp16 operands
// A fragment layout (mma.m16n8k16 A): [m16_blk(256)][k16(256)][lane(32)][a0..a3] (16B/lane)
__device__ __half g_act[(size_t)MPAD * DD];
// B fragment layout (R6, proven): [n8_blk(4000)][k16(256)][lane(32)][b0,b1] (8B/lane)
__device__ __half g_w[(size_t)VV * DD];

// ============================ helpers ============================
__device__ __forceinline__ uint32_t smem_u32(const void* p) {
    uint32_t a;
    asm("{ .reg .u64 t; cvta.to.shared.u64 t, %1; cvt.u32.u64 %0, t; }" : "=r"(a) : "l"(p));
    return a;
}
__device__ __forceinline__ void cp16(uint32_t dst, const void* src) {
    asm volatile("cp.async.cg.shared.global [%0], [%1], 16;" :: "r"(dst), "l"(src));
}
#define CP_COMMIT() asm volatile("cp.async.commit_group;" ::: "memory")
#define CP_WAIT2()  asm volatile("cp.async.wait_group 2;" ::: "memory")

__device__ __forceinline__ void mma_f16(float* d, const uint32_t* a, const uint32_t* b) {
    asm volatile(
        "mma.sync.aligned.m16n8k16.row.col.f32.f16.f16.f32 "
        "{%0,%1,%2,%3}, {%4,%5,%6,%7}, {%8,%9}, {%0,%1,%2,%3};"
        : "+f"(d[0]), "+f"(d[1]), "+f"(d[2]), "+f"(d[3])
        : "r"(a[0]), "r"(a[1]), "r"(a[2]), "r"(a[3]), "r"(b[0]), "r"(b[1]));
}

__device__ __forceinline__ uint32_t packh2(float lo, float hi) {
    __half2 h = __floats2half2_rn(lo, hi);
    return *reinterpret_cast<uint32_t*>(&h);
}
__device__ __forceinline__ void stcs2(uint32_t* p, uint32_t x, uint32_t y) {
    asm volatile("st.global.cs.v2.b32 [%0], {%1, %2};" :: "l"(p), "r"(x), "r"(y) : "memory");
}

// ============================ fused prolog kernel ============================
// (R14, proven: wperm at DRAM floor + rmsperm + labels, one launch)
#define WP_STRIDE 520
#define WP_BLOCKS 32000
#define PR_BLOCKS (WP_BLOCKS + MPAD)

__global__ void __launch_bounds__(256) prolog_kernel(
    const float* __restrict__ w, const float* __restrict__ x,
    const float* __restrict__ nw, uint32_t* __restrict__ ow,
    uint32_t* __restrict__ oa, const int* __restrict__ lab,
    float* __restrict__ out, long long rem) {
    __shared__ float s[8 * WP_STRIDE];
    int blk = blockIdx.x;
    int t = threadIdx.x;

    if (blk < WP_BLOCKS) {
        int n8b = blk >> 3;
        int kgbase = (blk & 7) * 32;
        {
            int r8 = t >> 5, f4 = t & 31;
            const float4* src = reinterpret_cast<const float4*>(
                w + ((size_t)(n8b * 8 + r8)) * DD + kgbase * 16);
            float* srow = s + r8 * WP_STRIDE;
#pragma unroll
            for (int it = 0; it < 4; ++it) {
                float4 v = __ldcs(src + it * 32 + f4);
                int ci = (it * 32 + f4) * 4;
                *reinterpret_cast<float4*>(srow + ci) = v;
            }
        }
        __syncthreads();
        {
            int ln = t & 31, w8 = t >> 5;
            int nl = ln >> 2, c = ln & 3;
            const float* srow = s + nl * WP_STRIDE;
#pragma unroll
            for (int j = 0; j < 4; ++j) {
                int kgl = w8 * 4 + j;
                float2 lo = *reinterpret_cast<const float2*>(srow + kgl * 16 + 2 * c);
                float2 hi = *reinterpret_cast<const float2*>(srow + kgl * 16 + 2 * c + 8);
                uint32_t b0 = packh2(lo.x, lo.y);
                uint32_t b1 = packh2(hi.x, hi.y);
                size_t ent = ((size_t)n8b * 256 + kgbase + kgl) * 32 + ln;
                stcs2(ow + ent * 2, b0, b1);
            }
        }
    } else {
        int r = blk - WP_BLOCKS;
        float vals[16];
        if (r < MROWS) {
            int b = r / (SS - 1);
            int sp = r - b * (SS - 1);
            if (t == 224) {
                int v = lab[(size_t)b * SS + sp + 1];
                size_t base = (size_t)MROWS * VV;
                if (rem >= 2LL * MROWS) {
                    reinterpret_cast<long long*>(out + base)[r] = (long long)v;
                } else if (rem >= (long long)MROWS) {
                    out[base + r] = (float)v;
                }
            }
            const float4* xr = reinterpret_cast<const float4*>(
                x + ((size_t)b * SS + sp) * DD + t * 16);
            const float4* wr = reinterpret_cast<const float4*>(nw + t * 16);
            float4 q[4];
            float acc = 0.f;
#pragma unroll
            for (int i = 0; i < 4; ++i) {
                q[i] = xr[i];
                acc += q[i].x * q[i].x + q[i].y * q[i].y + q[i].z * q[i].z + q[i].w * q[i].w;
            }
#pragma unroll
            for (int off = 16; off; off >>= 1) acc += __shfl_xor_sync(0xffffffffu, acc, off);
            if ((t & 31) == 0) s[t >> 5] = acc;
            __syncthreads();
            float tot = s[0] + s[1] + s[2] + s[3] + s[4] + s[5] + s[6] + s[7];
            float rs = rsqrtf(tot * (1.0f / DD) + 1e-6f);
#pragma unroll
            for (int i = 0; i < 4; ++i) {
                float4 wv = wr[i];
                vals[4 * i + 0] = q[i].x * rs * wv.x;
                vals[4 * i + 1] = q[i].y * rs * wv.y;
                vals[4 * i + 2] = q[i].z * rs * wv.z;
                vals[4 * i + 3] = q[i].w * rs * wv.w;
            }
        } else {
#pragma unroll
            for (int i = 0; i < 16; ++i) vals[i] = 0.f;
            __syncthreads();
        }
        int m16 = r >> 4, ri = r & 15;
        int slotb = ri >> 3;
        size_t laneBase = ((size_t)m16 * 256 + t) * 32 + (ri & 7) * 4;
#pragma unroll
        for (int c = 0; c < 4; ++c) {
            size_t li = (laneBase + c) * 4;
            oa[li + slotb]     = packh2(vals[2 * c],     vals[2 * c + 1]);
            oa[li + slotb + 2] = packh2(vals[2 * c + 8], vals[2 * c + 9]);
        }
    }
}

// ============================ GEMM kernel ============================
// Occupancy experiment: CTA tile 128(M) x 64(N), warp tile 32x32, 3 CTAs/SM
// (24 warps/SM = 6/SMSP vs 4 before). Pipeline structure EXACTLY R6:
// NSTG 3, wait2 + two syncthreads, load-after-compute, static stage counter.
#define NSTG      3
#define STG_BYTES 24576                 // A 16KB + B 8KB per stage
#define B_OFF     16384
#define KBLOCKS   (DD / 64)             // 64

__global__ void __launch_bounds__(256, 3) gemm_kernel(const __half* __restrict__ A,
                                                      const __half* __restrict__ B,
                                                      float* __restrict__ out) {
    extern __shared__ char smem[];
    uint32_t sbase = smem_u32(smem);
    int t = threadIdx.x;
    int lane = t & 31, wid = t >> 5;
    int wm = wid & 3, wn = wid >> 2;
    int m_tile = blockIdx.x & 31;       // m fastest: A (32MB fp16) L2-resident
    int n_tile = blockIdx.x >> 5;       // 500 n-tiles of 64

    const char* Ab = (const char*)A;
    const char* Bb = (const char*)B;

    auto load_stage = [&](int st, int kb) {
        uint32_t dstA = sbase + st * STG_BYTES;
        uint32_t dstB = dstA + B_OFF;
#pragma unroll
        for (int pp = 0; pp < 4; ++pp) {            // A: 1024 x 16B chunks
            int q = pp * 256 + t;
            int ln = q & 31, ks = (q >> 5) & 3, m16b = q >> 7;
            const char* src = Ab + ((((size_t)(m_tile * 8 + m16b) * 256 + kb * 4 + ks) * 32 + ln) << 4);
            cp16(dstA + (q << 4), src);
        }
#pragma unroll
        for (int pp = 0; pp < 2; ++pp) {            // B: 512 x 16B chunks (2 lanes each)
            int q = pp * 256 + t;
            int ln2 = q & 15, ks = (q >> 4) & 3, n8b = q >> 6;   // n8b 0..7
            const char* src = Bb + ((((size_t)(n_tile * 8 + n8b) * 256 + kb * 4 + ks) * 32 + ln2 * 2) << 3);
            cp16(dstB + (q << 4), src);
        }
    };

    float acc[2][4][4];
#pragma unroll
    for (int i = 0; i < 2; ++i)
#pragma unroll
        for (int j = 0; j < 4; ++j)
#pragma unroll
            for (int c = 0; c < 4; ++c) acc[i][j][c] = 0.f;

#pragma unroll
    for (int s = 0; s < NSTG; ++s) {
        load_stage(s, s);
        CP_COMMIT();
    }

    int st = 0;
    for (int kb = 0; kb < KBLOCKS; ++kb) {
        CP_WAIT2();
        __syncthreads();
        const uint4* Asp = reinterpret_cast<const uint4*>(smem + st * STG_BYTES);
        const uint2* Bsp = reinterpret_cast<const uint2*>(smem + st * STG_BYTES + B_OFF);
#pragma unroll
        for (int ks = 0; ks < 4; ++ks) {
            uint4 a[2];
            uint2 b[4];
#pragma unroll
            for (int i = 0; i < 2; ++i)
                a[i] = Asp[(((wm * 2 + i) * 4 + ks) * 32) + lane];
#pragma unroll
            for (int j = 0; j < 4; ++j)
                b[j] = Bsp[(((wn * 4 + j) * 4 + ks) * 32) + lane];
#pragma unroll
            for (int i = 0; i < 2; ++i)
#pragma unroll
                for (int j = 0; j < 4; ++j)
                    mma_f16(acc[i][j], (const uint32_t*)&a[i], (const uint32_t*)&b[j]);
        }
        __syncthreads();
        if (kb + NSTG < KBLOCKS) load_stage(st, kb + NSTG);
        CP_COMMIT();
        st = (st == NSTG - 1) ? 0 : st + 1;
    }

    // epilogue: fragment layout -> row-major fp32 logits
    int gq = lane >> 2, tq = lane & 3;
#pragma unroll
    for (int i = 0; i < 2; ++i) {
        int r0 = m_tile * 128 + wm * 32 + i * 16 + gq;
#pragma unroll
        for (int j = 0; j < 4; ++j) {
            int col = n_tile * 64 + wn * 32 + j * 8 + tq * 2;
            if (r0 < MROWS)
                *reinterpret_cast<float2*>(out + (size_t)r0 * VV + col) =
                    make_float2(acc[i][j][0], acc[i][j][1]);
            if (r0 + 8 < MROWS)
                *reinterpret_cast<float2*>(out + (size_t)(r0 + 8) * VV + col) =
                    make_float2(acc[i][j][2], acc[i][j][3]);
        }
    }
}

// ============================ host launcher ============================
extern "C" void kernel_launch(void* const* d_in, const int* in_sizes, int n_in,
                              void* d_out, int out_size) {
    const float* hs  = (const float*)d_in[0];
    const float* nw  = (const float*)d_in[1];
    const float* lmw = (const float*)d_in[2];
    const int*   lab = (const int*)d_in[4];
    float* out = (float*)d_out;

    void* act_ptr = nullptr; cudaGetSymbolAddress(&act_ptr, g_act);
    void* w_ptr   = nullptr; cudaGetSymbolAddress(&w_ptr, g_w);

    // fused prolog: wperm + rmsperm + labels in one launch
    long long rem = (long long)out_size - (long long)MROWS * VV;
    prolog_kernel<<<PR_BLOCKS, 256>>>(lmw, hs, nw, (uint32_t*)w_ptr,
                                      (uint32_t*)act_ptr, lab, out, rem);

    // GEMM: 32 m-tiles x 500 n-tiles, 3 CTAs/SM
    cudaFuncSetAttribute(gemm_kernel, cudaFuncAttributeMaxDynamicSharedMemorySize,
                         NSTG * STG_BYTES);
    gemm_kernel<<<32 * 500, 256, NSTG * STG_BYTES>>>((const __half*)act_ptr,
                                                     (const __half*)w_ptr, out);
}

// round 16
// speedup vs baseline: 1.0672x; 1.0672x over previous
#include <cuda_runtime.h>
#include <cuda_fp16.h>
#include <cstdint>

// ============================ problem constants ============================
#define SS 2048
#define DD 4096
#define VV 32000
#define MROWS 4094          // B*(S-1)
#define MPAD  4096          // padded GEMM M

// scratch (device globals — allocation-free rule), fp16 operands
// A fragment layout (mma.m16n8k16 A): [m16_blk(256)][k16(256)][lane(32)][a0..a3] (16B/lane)
__device__ __half g_act[(size_t)MPAD * DD];
// B fragment layout (R6, proven): [n8_blk(4000)][k16(256)][lane(32)][b0,b1] (8B/lane)
__device__ __half g_w[(size_t)VV * DD];

// ============================ helpers ============================
__device__ __forceinline__ uint32_t smem_u32(const void* p) {
    uint32_t a;
    asm("{ .reg .u64 t; cvta.to.shared.u64 t, %1; cvt.u32.u64 %0, t; }" : "=r"(a) : "l"(p));
    return a;
}
__device__ __forceinline__ void cp16(uint32_t dst, const void* src) {
    asm volatile("cp.async.cg.shared.global [%0], [%1], 16;" :: "r"(dst), "l"(src));
}
#define CP_COMMIT() asm volatile("cp.async.commit_group;" ::: "memory")
#define CP_WAIT2()  asm volatile("cp.async.wait_group 2;" ::: "memory")

__device__ __forceinline__ void mma_f16(float* d, const uint32_t* a, const uint32_t* b) {
    asm volatile(
        "mma.sync.aligned.m16n8k16.row.col.f32.f16.f16.f32 "
        "{%0,%1,%2,%3}, {%4,%5,%6,%7}, {%8,%9}, {%0,%1,%2,%3};"
        : "+f"(d[0]), "+f"(d[1]), "+f"(d[2]), "+f"(d[3])
        : "r"(a[0]), "r"(a[1]), "r"(a[2]), "r"(a[3]), "r"(b[0]), "r"(b[1]));
}

__device__ __forceinline__ uint32_t packh2(float lo, float hi) {
    __half2 h = __floats2half2_rn(lo, hi);
    return *reinterpret_cast<uint32_t*>(&h);
}
__device__ __forceinline__ void stcs2(uint32_t* p, uint32_t x, uint32_t y) {
    asm volatile("st.global.cs.v2.b32 [%0], {%1, %2};" :: "l"(p), "r"(x), "r"(y) : "memory");
}

// ============================ fused prolog kernel ============================
// Block order: rms blocks FIRST [0, MPAD), wperm after [MPAD, MPAD+32000).
// The long uniform wperm DRAM stream forms the kernel tail; all rms work
// (different input stream) overlaps under it.
#define WP_STRIDE 520
#define WP_BLOCKS 32000
#define PR_BLOCKS (MPAD + WP_BLOCKS)

__global__ void __launch_bounds__(256) prolog_kernel(
    const float* __restrict__ w, const float* __restrict__ x,
    const float* __restrict__ nw, uint32_t* __restrict__ ow,
    uint32_t* __restrict__ oa, const int* __restrict__ lab,
    float* __restrict__ out, long long rem) {
    __shared__ float s[8 * WP_STRIDE];
    int blk = blockIdx.x;
    int t = threadIdx.x;

    if (blk >= MPAD) {
        // ---------------- wperm body (exact R13/R14, proven DRAM-floor) ----------------
        int wblk = blk - MPAD;
        int n8b = wblk >> 3;
        int kgbase = (wblk & 7) * 32;
        {
            int r8 = t >> 5, f4 = t & 31;
            const float4* src = reinterpret_cast<const float4*>(
                w + ((size_t)(n8b * 8 + r8)) * DD + kgbase * 16);
            float* srow = s + r8 * WP_STRIDE;
#pragma unroll
            for (int it = 0; it < 4; ++it) {
                float4 v = __ldcs(src + it * 32 + f4);
                int ci = (it * 32 + f4) * 4;
                *reinterpret_cast<float4*>(srow + ci) = v;
            }
        }
        __syncthreads();
        {
            int ln = t & 31, w8 = t >> 5;
            int nl = ln >> 2, c = ln & 3;
            const float* srow = s + nl * WP_STRIDE;
#pragma unroll
            for (int j = 0; j < 4; ++j) {
                int kgl = w8 * 4 + j;
                float2 lo = *reinterpret_cast<const float2*>(srow + kgl * 16 + 2 * c);
                float2 hi = *reinterpret_cast<const float2*>(srow + kgl * 16 + 2 * c + 8);
                uint32_t b0 = packh2(lo.x, lo.y);
                uint32_t b1 = packh2(hi.x, hi.y);
                size_t ent = ((size_t)n8b * 256 + kgbase + kgl) * 32 + ln;
                stcs2(ow + ent * 2, b0, b1);
            }
        }
    } else {
        // ---------------- rmsperm body (exact R12-R14, proven) ----------------
        int r = blk;
        float vals[16];
        if (r < MROWS) {
            int b = r / (SS - 1);
            int sp = r - b * (SS - 1);
            if (t == 224) {   // labels: one thread per block
                int v = lab[(size_t)b * SS + sp + 1];
                size_t base = (size_t)MROWS * VV;
                if (rem >= 2LL * MROWS) {
                    reinterpret_cast<long long*>(out + base)[r] = (long long)v;
                } else if (rem >= (long long)MROWS) {
                    out[base + r] = (float)v;   // float32 tail (R4-proven layout)
                }
            }
            const float4* xr = reinterpret_cast<const float4*>(
                x + ((size_t)b * SS + sp) * DD + t * 16);
            const float4* wr = reinterpret_cast<const float4*>(nw + t * 16);
            float4 q[4];
            float acc = 0.f;
#pragma unroll
            for (int i = 0; i < 4; ++i) {
                q[i] = __ldcs(xr + i);          // read-once stream: evict-first
                acc += q[i].x * q[i].x + q[i].y * q[i].y + q[i].z * q[i].z + q[i].w * q[i].w;
            }
#pragma unroll
            for (int off = 16; off; off >>= 1) acc += __shfl_xor_sync(0xffffffffu, acc, off);
            if ((t & 31) == 0) s[t >> 5] = acc;
            __syncthreads();
            float tot = s[0] + s[1] + s[2] + s[3] + s[4] + s[5] + s[6] + s[7];
            float rs = rsqrtf(tot * (1.0f / DD) + 1e-6f);
#pragma unroll
            for (int i = 0; i < 4; ++i) {
                float4 wv = wr[i];
                vals[4 * i + 0] = q[i].x * rs * wv.x;
                vals[4 * i + 1] = q[i].y * rs * wv.y;
                vals[4 * i + 2] = q[i].z * rs * wv.z;
                vals[4 * i + 3] = q[i].w * rs * wv.w;
            }
        } else {
#pragma unroll
            for (int i = 0; i < 16; ++i) vals[i] = 0.f;
            __syncthreads();   // keep barrier count uniform within this block
        }
        int m16 = r >> 4, ri = r & 15;
        int slotb = ri >> 3;
        size_t laneBase = ((size_t)m16 * 256 + t) * 32 + (ri & 7) * 4;
#pragma unroll
        for (int c = 0; c < 4; ++c) {
            size_t li = (laneBase + c) * 4;
            oa[li + slotb]     = packh2(vals[2 * c],     vals[2 * c + 1]);
            oa[li + slotb + 2] = packh2(vals[2 * c + 8], vals[2 * c + 9]);
        }
    }
}

// ============================ GEMM kernel ============================
// EXACT R6/R13/R14 (proven optimum, analytically at the tensor/L1 balance
// point): grid 8000, CTA 128x128, kBlock 64, NSTG 3, wait2 + two syncthreads,
// load-after-compute, static stage counter. DO NOT TOUCH.
#define NSTG      3
#define STG_BYTES 32768                 // A 16KB + B 16KB per stage
#define KBLOCKS   (DD / 64)             // 64

__global__ void __launch_bounds__(256, 2) gemm_kernel(const __half* __restrict__ A,
                                                      const __half* __restrict__ B,
                                                      float* __restrict__ out) {
    extern __shared__ char smem[];
    uint32_t sbase = smem_u32(smem);
    int t = threadIdx.x;
    int lane = t & 31, wid = t >> 5;
    int wm = wid & 3, wn = wid >> 2;
    int m_tile = blockIdx.x & 31;       // m fastest: A (32MB fp16) L2-resident
    int n_tile = blockIdx.x >> 5;

    const char* Ab = (const char*)A;
    const char* Bb = (const char*)B;

    auto load_stage = [&](int st, int kb) {
        uint32_t dstA = sbase + st * STG_BYTES;
        uint32_t dstB = dstA + 16384;
#pragma unroll
        for (int pp = 0; pp < 4; ++pp) {            // A: 1024 x 16B chunks
            int q = pp * 256 + t;
            int ln = q & 31, ks = (q >> 5) & 3, m16b = q >> 7;
            const char* src = Ab + ((((size_t)(m_tile * 8 + m16b) * 256 + kb * 4 + ks) * 32 + ln) << 4);
            cp16(dstA + (q << 4), src);
        }
#pragma unroll
        for (int pp = 0; pp < 4; ++pp) {            // B: 1024 x 16B chunks (2 lanes each)
            int q = pp * 256 + t;
            int ln2 = q & 15, ks = (q >> 4) & 3, n8b = q >> 6;
            const char* src = Bb + ((((size_t)(n_tile * 16 + n8b) * 256 + kb * 4 + ks) * 32 + ln2 * 2) << 3);
            cp16(dstB + (q << 4), src);
        }
    };

    float acc[2][8][4];
#pragma unroll
    for (int i = 0; i < 2; ++i)
#pragma unroll
        for (int j = 0; j < 8; ++j)
#pragma unroll
            for (int c = 0; c < 4; ++c) acc[i][j][c] = 0.f;

#pragma unroll
    for (int s = 0; s < NSTG; ++s) {
        load_stage(s, s);
        CP_COMMIT();
    }

    int st = 0;
    for (int kb = 0; kb < KBLOCKS; ++kb) {
        CP_WAIT2();
        __syncthreads();
        const uint4* Asp = reinterpret_cast<const uint4*>(smem + st * STG_BYTES);
        const uint2* Bsp = reinterpret_cast<const uint2*>(smem + st * STG_BYTES + 16384);
#pragma unroll
        for (int ks = 0; ks < 4; ++ks) {
            uint4 a[2];
            uint2 b[8];
#pragma unroll
            for (int i = 0; i < 2; ++i)
                a[i] = Asp[(((wm * 2 + i) * 4 + ks) * 32) + lane];
#pragma unroll
            for (int j = 0; j < 8; ++j)
                b[j] = Bsp[(((wn * 8 + j) * 4 + ks) * 32) + lane];
#pragma unroll
            for (int i = 0; i < 2; ++i)
#pragma unroll
                for (int j = 0; j < 8; ++j)
                    mma_f16(acc[i][j], (const uint32_t*)&a[i], (const uint32_t*)&b[j]);
        }
        __syncthreads();
        if (kb + NSTG < KBLOCKS) load_stage(st, kb + NSTG);
        CP_COMMIT();
        st = (st == NSTG - 1) ? 0 : st + 1;
    }

    // epilogue: fragment layout -> row-major fp32 logits (exact R6)
    int gq = lane >> 2, tq = lane & 3;
#pragma unroll
    for (int i = 0; i < 2; ++i) {
        int r0 = m_tile * 128 + wm * 32 + i * 16 + gq;
#pragma unroll
        for (int j = 0; j < 8; ++j) {
            int col = n_tile * 128 + wn * 64 + j * 8 + tq * 2;
            if (r0 < MROWS)
                *reinterpret_cast<float2*>(out + (size_t)r0 * VV + col) =
                    make_float2(acc[i][j][0], acc[i][j][1]);
            if (r0 + 8 < MROWS)
                *reinterpret_cast<float2*>(out + (size_t)(r0 + 8) * VV + col) =
                    make_float2(acc[i][j][2], acc[i][j][3]);
        }
    }
}

// ============================ host launcher ============================
extern "C" void kernel_launch(void* const* d_in, const int* in_sizes, int n_in,
                              void* d_out, int out_size) {
    const float* hs  = (const float*)d_in[0];
    const float* nw  = (const float*)d_in[1];
    const float* lmw = (const float*)d_in[2];
    const int*   lab = (const int*)d_in[4];
    float* out = (float*)d_out;

    void* act_ptr = nullptr; cudaGetSymbolAddress(&act_ptr, g_act);
    void* w_ptr   = nullptr; cudaGetSymbolAddress(&w_ptr, g_w);

    // fused prolog: rms blocks first, wperm stream forms the tail
    long long rem = (long long)out_size - (long long)MROWS * VV;
    prolog_kernel<<<PR_BLOCKS, 256>>>(lmw, hs, nw, (uint32_t*)w_ptr,
                                      (uint32_t*)act_ptr, lab, out, rem);

    // GEMM: 32 m-tiles x 250 n-tiles (proven config)
    cudaFuncSetAttribute(gemm_kernel, cudaFuncAttributeMaxDynamicSharedMemorySize,
                         NSTG * STG_BYTES);
    gemm_kernel<<<32 * 250, 256, NSTG * STG_BYTES>>>((const __half*)act_ptr,
                                                     (const __half*)w_ptr, out);
}

// round 17
// speedup vs baseline: 1.1121x; 1.0421x over previous
#include <cuda_runtime.h>
#include <cuda_fp16.h>
#include <cstdint>

// ============================ problem constants ============================
#define SS 2048
#define DD 4096
#define VV 32000
#define MROWS 4094          // B*(S-1)
#define MPAD  4096          // padded GEMM M

// scratch (device globals — allocation-free rule), fp16 operands
// A fragment layout (mma.m16n8k16 A): [m16_blk(256)][k16(256)][lane(32)][a0..a3] (16B/lane)
__device__ __half g_act[(size_t)MPAD * DD];
// B fragment layout (R6, proven): [n8_blk(4000)][k16(256)][lane(32)][b0,b1] (8B/lane)
__device__ __half g_w[(size_t)VV * DD];

// ============================ helpers ============================
__device__ __forceinline__ uint32_t smem_u32(const void* p) {
    uint32_t a;
    asm("{ .reg .u64 t; cvta.to.shared.u64 t, %1; cvt.u32.u64 %0, t; }" : "=r"(a) : "l"(p));
    return a;
}
__device__ __forceinline__ void cp16(uint32_t dst, const void* src) {
    asm volatile("cp.async.cg.shared.global [%0], [%1], 16;" :: "r"(dst), "l"(src));
}
#define CP_COMMIT() asm volatile("cp.async.commit_group;" ::: "memory")
#define CP_WAIT2()  asm volatile("cp.async.wait_group 2;" ::: "memory")

__device__ __forceinline__ void mma_f16(float* d, const uint32_t* a, const uint32_t* b) {
    asm volatile(
        "mma.sync.aligned.m16n8k16.row.col.f32.f16.f16.f32 "
        "{%0,%1,%2,%3}, {%4,%5,%6,%7}, {%8,%9}, {%0,%1,%2,%3};"
        : "+f"(d[0]), "+f"(d[1]), "+f"(d[2]), "+f"(d[3])
        : "r"(a[0]), "r"(a[1]), "r"(a[2]), "r"(a[3]), "r"(b[0]), "r"(b[1]));
}

__device__ __forceinline__ uint32_t packh2(float lo, float hi) {
    __half2 h = __floats2half2_rn(lo, hi);
    return *reinterpret_cast<uint32_t*>(&h);
}
__device__ __forceinline__ void stcs2(uint32_t* p, uint32_t x, uint32_t y) {
    asm volatile("st.global.cs.v2.b32 [%0], {%1, %2};" :: "l"(p), "r"(x), "r"(y) : "memory");
}

// ============================ fused prolog kernel ============================
// (R16, proven: rms blocks first, wperm DRAM-floor stream as tail)
#define WP_STRIDE 520
#define WP_BLOCKS 32000
#define PR_BLOCKS (MPAD + WP_BLOCKS)

__global__ void __launch_bounds__(256) prolog_kernel(
    const float* __restrict__ w, const float* __restrict__ x,
    const float* __restrict__ nw, uint32_t* __restrict__ ow,
    uint32_t* __restrict__ oa, const int* __restrict__ lab,
    float* __restrict__ out, long long rem) {
    __shared__ float s[8 * WP_STRIDE];
    int blk = blockIdx.x;
    int t = threadIdx.x;

    if (blk >= MPAD) {
        // ---------------- wperm body (exact R13-R16, DRAM-floor) ----------------
        int wblk = blk - MPAD;
        int n8b = wblk >> 3;
        int kgbase = (wblk & 7) * 32;
        {
            int r8 = t >> 5, f4 = t & 31;
            const float4* src = reinterpret_cast<const float4*>(
                w + ((size_t)(n8b * 8 + r8)) * DD + kgbase * 16);
            float* srow = s + r8 * WP_STRIDE;
#pragma unroll
            for (int it = 0; it < 4; ++it) {
                float4 v = __ldcs(src + it * 32 + f4);
                int ci = (it * 32 + f4) * 4;
                *reinterpret_cast<float4*>(srow + ci) = v;
            }
        }
        __syncthreads();
        {
            int ln = t & 31, w8 = t >> 5;
            int nl = ln >> 2, c = ln & 3;
            const float* srow = s + nl * WP_STRIDE;
#pragma unroll
            for (int j = 0; j < 4; ++j) {
                int kgl = w8 * 4 + j;
                float2 lo = *reinterpret_cast<const float2*>(srow + kgl * 16 + 2 * c);
                float2 hi = *reinterpret_cast<const float2*>(srow + kgl * 16 + 2 * c + 8);
                uint32_t b0 = packh2(lo.x, lo.y);
                uint32_t b1 = packh2(hi.x, hi.y);
                size_t ent = ((size_t)n8b * 256 + kgbase + kgl) * 32 + ln;
                stcs2(ow + ent * 2, b0, b1);
            }
        }
    } else {
        // ---------------- rmsperm body (exact R12-R16, proven) ----------------
        int r = blk;
        float vals[16];
        if (r < MROWS) {
            int b = r / (SS - 1);
            int sp = r - b * (SS - 1);
            if (t == 224) {   // labels: one thread per block
                int v = lab[(size_t)b * SS + sp + 1];
                size_t base = (size_t)MROWS * VV;
                if (rem >= 2LL * MROWS) {
                    reinterpret_cast<long long*>(out + base)[r] = (long long)v;
                } else if (rem >= (long long)MROWS) {
                    out[base + r] = (float)v;   // float32 tail (R4-proven layout)
                }
            }
            const float4* xr = reinterpret_cast<const float4*>(
                x + ((size_t)b * SS + sp) * DD + t * 16);
            const float4* wr = reinterpret_cast<const float4*>(nw + t * 16);
            float4 q[4];
            float acc = 0.f;
#pragma unroll
            for (int i = 0; i < 4; ++i) {
                q[i] = __ldcs(xr + i);
                acc += q[i].x * q[i].x + q[i].y * q[i].y + q[i].z * q[i].z + q[i].w * q[i].w;
            }
#pragma unroll
            for (int off = 16; off; off >>= 1) acc += __shfl_xor_sync(0xffffffffu, acc, off);
            if ((t & 31) == 0) s[t >> 5] = acc;
            __syncthreads();
            float tot = s[0] + s[1] + s[2] + s[3] + s[4] + s[5] + s[6] + s[7];
            float rs = rsqrtf(tot * (1.0f / DD) + 1e-6f);
#pragma unroll
            for (int i = 0; i < 4; ++i) {
                float4 wv = wr[i];
                vals[4 * i + 0] = q[i].x * rs * wv.x;
                vals[4 * i + 1] = q[i].y * rs * wv.y;
                vals[4 * i + 2] = q[i].z * rs * wv.z;
                vals[4 * i + 3] = q[i].w * rs * wv.w;
            }
        } else {
#pragma unroll
            for (int i = 0; i < 16; ++i) vals[i] = 0.f;
            __syncthreads();
        }
        int m16 = r >> 4, ri = r & 15;
        int slotb = ri >> 3;
        size_t laneBase = ((size_t)m16 * 256 + t) * 32 + (ri & 7) * 4;
#pragma unroll
        for (int c = 0; c < 4; ++c) {
            size_t li = (laneBase + c) * 4;
            oa[li + slotb]     = packh2(vals[2 * c],     vals[2 * c + 1]);
            oa[li + slotb + 2] = packh2(vals[2 * c + 8], vals[2 * c + 9]);
        }
    }
}

// ============================ GEMM kernel ============================
// R6 structure (grid 8000, CTA 128x128, kBlock 64, NSTG 3, wait2 + two
// syncthreads, load-after-compute). ONE change vs R16: warp arrangement
// 4m x 2n -> 2m x 4n (warp tile 64x32). Same regs, same smem image, same
// LDS bytes; 8 LDS instr/ks instead of 10.
#define NSTG      3
#define STG_BYTES 32768                 // A 16KB + B 16KB per stage
#define KBLOCKS   (DD / 64)             // 64

__global__ void __launch_bounds__(256, 2) gemm_kernel(const __half* __restrict__ A,
                                                      const __half* __restrict__ B,
                                                      float* __restrict__ out) {
    extern __shared__ char smem[];
    uint32_t sbase = smem_u32(smem);
    int t = threadIdx.x;
    int lane = t & 31, wid = t >> 5;
    int wm = wid & 1, wn = wid >> 1;    // 2m x 4n
    int m_tile = blockIdx.x & 31;       // m fastest: A (32MB fp16) L2-resident
    int n_tile = blockIdx.x >> 5;

    const char* Ab = (const char*)A;
    const char* Bb = (const char*)B;

    auto load_stage = [&](int st, int kb) {
        uint32_t dstA = sbase + st * STG_BYTES;
        uint32_t dstB = dstA + 16384;
#pragma unroll
        for (int pp = 0; pp < 4; ++pp) {            // A: 1024 x 16B chunks
            int q = pp * 256 + t;
            int ln = q & 31, ks = (q >> 5) & 3, m16b = q >> 7;
            const char* src = Ab + ((((size_t)(m_tile * 8 + m16b) * 256 + kb * 4 + ks) * 32 + ln) << 4);
            cp16(dstA + (q << 4), src);
        }
#pragma unroll
        for (int pp = 0; pp < 4; ++pp) {            // B: 1024 x 16B chunks (2 lanes each)
            int q = pp * 256 + t;
            int ln2 = q & 15, ks = (q >> 4) & 3, n8b = q >> 6;
            const char* src = Bb + ((((size_t)(n_tile * 16 + n8b) * 256 + kb * 4 + ks) * 32 + ln2 * 2) << 3);
            cp16(dstB + (q << 4), src);
        }
    };

    float acc[4][4][4];
#pragma unroll
    for (int i = 0; i < 4; ++i)
#pragma unroll
        for (int j = 0; j < 4; ++j)
#pragma unroll
            for (int c = 0; c < 4; ++c) acc[i][j][c] = 0.f;

#pragma unroll
    for (int s = 0; s < NSTG; ++s) {
        load_stage(s, s);
        CP_COMMIT();
    }

    int st = 0;
    for (int kb = 0; kb < KBLOCKS; ++kb) {
        CP_WAIT2();
        __syncthreads();
        const uint4* Asp = reinterpret_cast<const uint4*>(smem + st * STG_BYTES);
        const uint2* Bsp = reinterpret_cast<const uint2*>(smem + st * STG_BYTES + 16384);
#pragma unroll
        for (int ks = 0; ks < 4; ++ks) {
            uint4 a[4];                              // 4 lds.128 (m16 blocks of this warp)
            uint2 b[4];                              // 4 lds.64  (n8 blocks of this warp)
#pragma unroll
            for (int i = 0; i < 4; ++i)
                a[i] = Asp[(((wm * 4 + i) * 4 + ks) * 32) + lane];
#pragma unroll
            for (int j = 0; j < 4; ++j)
                b[j] = Bsp[(((wn * 4 + j) * 4 + ks) * 32) + lane];
#pragma unroll
            for (int i = 0; i < 4; ++i)
#pragma unroll
                for (int j = 0; j < 4; ++j)
                    mma_f16(acc[i][j], (const uint32_t*)&a[i], (const uint32_t*)&b[j]);
        }
        __syncthreads();
        if (kb + NSTG < KBLOCKS) load_stage(st, kb + NSTG);
        CP_COMMIT();
        st = (st == NSTG - 1) ? 0 : st + 1;
    }

    // epilogue: fragment layout -> row-major fp32 logits (2m x 4n mapping)
    int gq = lane >> 2, tq = lane & 3;
#pragma unroll
    for (int i = 0; i < 4; ++i) {
        int r0 = m_tile * 128 + wm * 64 + i * 16 + gq;
#pragma unroll
        for (int j = 0; j < 4; ++j) {
            int col = n_tile * 128 + wn * 32 + j * 8 + tq * 2;
            if (r0 < MROWS)
                *reinterpret_cast<float2*>(out + (size_t)r0 * VV + col) =
                    make_float2(acc[i][j][0], acc[i][j][1]);
            if (r0 + 8 < MROWS)
                *reinterpret_cast<float2*>(out + (size_t)(r0 + 8) * VV + col) =
                    make_float2(acc[i][j][2], acc[i][j][3]);
        }
    }
}

// ============================ host launcher ============================
extern "C" void kernel_launch(void* const* d_in, const int* in_sizes, int n_in,
                              void* d_out, int out_size) {
    const float* hs  = (const float*)d_in[0];
    const float* nw  = (const float*)d_in[1];
    const float* lmw = (const float*)d_in[2];
    const int*   lab = (const int*)d_in[4];
    float* out = (float*)d_out;

    void* act_ptr = nullptr; cudaGetSymbolAddress(&act_ptr, g_act);
    void* w_ptr   = nullptr; cudaGetSymbolAddress(&w_ptr, g_w);

    // fused prolog: rms blocks first, wperm stream forms the tail
    long long rem = (long long)out_size - (long long)MROWS * VV;
    prolog_kernel<<<PR_BLOCKS, 256>>>(lmw, hs, nw, (uint32_t*)w_ptr,
                                      (uint32_t*)act_ptr, lab, out, rem);

    // GEMM: 32 m-tiles x 250 n-tiles (proven grid)
    cudaFuncSetAttribute(gemm_kernel, cudaFuncAttributeMaxDynamicSharedMemorySize,
                         NSTG * STG_BYTES);
    gemm_kernel<<<32 * 250, 256, NSTG * STG_BYTES>>>((const __half*)act_ptr,
                                                     (const __half*)w_ptr, out);
}